// round 7
// baseline (speedup 1.0000x reference)
#include <cuda_runtime.h>
#include <cstdint>

// ---------------- problem constants ----------------
#define N_ATOMS 100000
#define DIN     120
#define HID     128
#define NMOL    2000
#define TILE    64                  // atoms per CTA
#define NTHR    256                 // 8 warps (2 per SMSP)
#define NBLK    1566                // ceil((100000 + 3*63)/64)
#define PTOT    (NBLK * TILE)
#define LW      132                 // A rows [atom][k] stride
#define LWC     132                 // B rows [k][col] stride

// ---------------- device scratch ----------------
__device__ float g_flat_d[N_ATOMS * DIN];
__device__ int   perm_d[PTOT];
__device__ int   counts_d[3];
__device__ int   cursor_d[3];

__device__ __forceinline__ int elem_of(int z) {
    return (z == 1) ? 0 : ((z == 6) ? 1 : 2);
}

__device__ __forceinline__ float fast_tanh(float x) {
    x = fminf(15.f, fmaxf(-15.f, x));
    float e = __expf(2.f * x);
    return __fdividef(e - 1.f, e + 1.f);
}

// ---------------- prelude kernels (3 launches before k_mlp) ----------------
__global__ void k_init(float* __restrict__ out) {
    int i = blockIdx.x * blockDim.x + threadIdx.x;
    if (i < NMOL + 3 * N_ATOMS) out[i] = 0.f;
    if (i < PTOT) perm_d[i] = -1;
    if (i < 3) { counts_d[i] = 0; cursor_d[i] = 0; }
}

__global__ void k_count(const int* __restrict__ z) {
    __shared__ int loc[3];
    int t = threadIdx.x;
    if (t < 3) loc[t] = 0;
    __syncthreads();
    int i = blockIdx.x * blockDim.x + t;
    if (i < N_ATOMS) atomicAdd(&loc[elem_of(z[i])], 1);
    __syncthreads();
    if (t < 3 && loc[t] > 0) atomicAdd(&counts_d[t], loc[t]);
}

// offsets folded in: each block derives element bases from counts_d
__global__ void k_build(const int* __restrict__ z) {
    __shared__ int loc[3], base[3];
    int t = threadIdx.x;
    if (t < 3) loc[t] = 0;
    __syncthreads();
    int i = blockIdx.x * blockDim.x + t;
    int e = -1, r = 0;
    if (i < N_ATOMS) { e = elem_of(z[i]); r = atomicAdd(&loc[e], 1); }
    __syncthreads();
    if (t < 3) base[t] = (loc[t] > 0) ? atomicAdd(&cursor_d[t], loc[t]) : 0;
    __syncthreads();
    if (i < N_ATOMS) {
        int r0 = (counts_d[0] + TILE - 1) / TILE * TILE;
        int r1 = (counts_d[1] + TILE - 1) / TILE * TILE;
        int eb = (e == 0) ? 0 : ((e == 1) ? r0 : r0 + r1);
        int p = eb + base[e] + r;
        if (p >= 0 && p < PTOT) perm_d[p] = i;
    }
}

// ---------------- weight staging ----------------
// Forward: WB[k][c] = W[k][c]  (native copy, zero-pad k >= Krows)
__device__ __forceinline__ void stage_fwd(float* __restrict__ WB,
                                          const float* __restrict__ W,
                                          int Krows, int tid) {
    for (int idx = tid; idx < 4096; idx += NTHR) {
        int k = idx >> 5, c = (idx & 31) * 4;
        float4 v = make_float4(0.f, 0.f, 0.f, 0.f);
        if (k < Krows)
            v = __ldg(reinterpret_cast<const float4*>(W + k * HID + c));
        *reinterpret_cast<float4*>(WB + k * LWC + c) = v;
    }
}
// Backward: WB[k][m] = W[m][k]  (transpose; zero-pad m >= Mrows)
__device__ __forceinline__ void stage_bwd(float* __restrict__ WB,
                                          const float* __restrict__ W,
                                          int Mrows, int tid) {
    for (int idx = tid; idx < 4096; idx += NTHR) {
        int m = idx & 127, k = (idx >> 7) * 4;
        float4 v = make_float4(0.f, 0.f, 0.f, 0.f);
        if (m < Mrows)
            v = __ldg(reinterpret_cast<const float4*>(W + m * HID + k));
        WB[(k + 0) * LWC + m] = v.x;
        WB[(k + 1) * LWC + m] = v.y;
        WB[(k + 2) * LWC + m] = v.z;
        WB[(k + 3) * LWC + m] = v.w;
    }
}

// ---------------- FFMA GEMM core: thread = 8 atoms x 4 cols ----------------
__device__ __forceinline__ void gemm(
    const float* __restrict__ As, const float* __restrict__ Bs,
    int K4, int arow0, int c0, float acc[8][4])
{
#pragma unroll
    for (int ai = 0; ai < 8; ai++)
#pragma unroll
        for (int ci = 0; ci < 4; ci++) acc[ai][ci] = 0.f;

#pragma unroll 2
    for (int k4 = 0; k4 < K4; k4++) {
        int k = k4 * 4;
        float4 wv0 = *reinterpret_cast<const float4*>(Bs + (k + 0) * LWC + c0);
        float4 wv1 = *reinterpret_cast<const float4*>(Bs + (k + 1) * LWC + c0);
        float4 wv2 = *reinterpret_cast<const float4*>(Bs + (k + 2) * LWC + c0);
        float4 wv3 = *reinterpret_cast<const float4*>(Bs + (k + 3) * LWC + c0);
#pragma unroll
        for (int ai = 0; ai < 8; ai++) {
            float4 x = *reinterpret_cast<const float4*>(As + (arow0 + ai) * LW + k);
            acc[ai][0] = fmaf(x.x, wv0.x, acc[ai][0]);
            acc[ai][1] = fmaf(x.x, wv0.y, acc[ai][1]);
            acc[ai][2] = fmaf(x.x, wv0.z, acc[ai][2]);
            acc[ai][3] = fmaf(x.x, wv0.w, acc[ai][3]);
            acc[ai][0] = fmaf(x.y, wv1.x, acc[ai][0]);
            acc[ai][1] = fmaf(x.y, wv1.y, acc[ai][1]);
            acc[ai][2] = fmaf(x.y, wv1.z, acc[ai][2]);
            acc[ai][3] = fmaf(x.y, wv1.w, acc[ai][3]);
            acc[ai][0] = fmaf(x.z, wv2.x, acc[ai][0]);
            acc[ai][1] = fmaf(x.z, wv2.y, acc[ai][1]);
            acc[ai][2] = fmaf(x.z, wv2.z, acc[ai][2]);
            acc[ai][3] = fmaf(x.z, wv2.w, acc[ai][3]);
            acc[ai][0] = fmaf(x.w, wv3.x, acc[ai][0]);
            acc[ai][1] = fmaf(x.w, wv3.y, acc[ai][1]);
            acc[ai][2] = fmaf(x.w, wv3.z, acc[ai][2]);
            acc[ai][3] = fmaf(x.w, wv3.w, acc[ai][3]);
        }
    }
}

// ---------------- fused MLP fwd+bwd ----------------
// dyn smem: B0[64*132] | B1[64*132] | B2[64*132] | WB[128*132]   (~165 KB)
#define SMEM_DYN ((3 * TILE * LW + HID * LWC) * 4)

__global__ __launch_bounds__(NTHR) void k_mlp(
    const int* __restrict__ z, const float* __restrict__ fp,
    const int* __restrict__ img,
    const float* __restrict__ W1, const float* __restrict__ b1,
    const float* __restrict__ W2, const float* __restrict__ b2,
    const float* __restrict__ W3, const float* __restrict__ b3,
    const float* __restrict__ W4, const float* __restrict__ b4,
    float* __restrict__ energy)
{
    extern __shared__ float sm[];
    float* B0 = sm;                    // X -> dp3
    float* B1 = B0 + TILE * LW;        // h1 -> dp1
    float* B2 = B1 + TILE * LW;        // h2 -> dp2
    float* WB = B2 + TILE * LW;        // weights, K-major [k][col]

    __shared__ int s_aid[TILE];
    __shared__ int s_e;

    int tid = threadIdx.x;
    int wid = tid >> 5, lane = tid & 31;
    int arow0 = wid * 8;               // warp owns 8 atoms
    int c0 = lane * 4;                 // lane owns 4 cols

    if (tid == 0) s_e = -1;
    __syncthreads();
    if (tid < TILE) {
        int a = perm_d[blockIdx.x * TILE + tid];
        s_aid[tid] = a;
        if (a >= 0) s_e = elem_of(__ldg(z + a));
    }
    __syncthreads();
    if (s_e < 0) return;
    int e = s_e;

    const float* W1e = W1 + e * DIN * HID;
    const float* W2e = W2 + e * HID * HID;
    const float* W3e = W3 + e * HID * HID;
    const float* W4e = W4 + e * HID;
    const float* b1e = b1 + e * HID;
    const float* b2e = b2 + e * HID;
    const float* b3e = b3 + e * HID;
    float        b4e = __ldg(b4 + e);

    // stage X [atom][k] (zero-padded) and W1 forward
    for (int idx = tid; idx < 2048; idx += NTHR) {
        int a = idx >> 5, k = (idx & 31) * 4;
        int aid = s_aid[a];
        float4 v = make_float4(0.f, 0.f, 0.f, 0.f);
        if (aid >= 0 && k < DIN)
            v = __ldg(reinterpret_cast<const float4*>(fp + aid * DIN + k));
        *reinterpret_cast<float4*>(B0 + a * LW + k) = v;
    }
    stage_fwd(WB, W1e, DIN, tid);
    __syncthreads();

    float acc[8][4];

    // ======== Pass 1: h1 = tanh(X @ W1 + b1) -> B1  (K=120) ========
    gemm(B0, WB, 30, arow0, c0, acc);
    __syncthreads();
    {
        float4 bb = __ldg(reinterpret_cast<const float4*>(b1e + c0));
#pragma unroll
        for (int ai = 0; ai < 8; ai++) {
            float4 h;
            h.x = fast_tanh(acc[ai][0] + bb.x);
            h.y = fast_tanh(acc[ai][1] + bb.y);
            h.z = fast_tanh(acc[ai][2] + bb.z);
            h.w = fast_tanh(acc[ai][3] + bb.w);
            *reinterpret_cast<float4*>(B1 + (arow0 + ai) * LW + c0) = h;
        }
    }
    stage_fwd(WB, W2e, HID, tid);
    __syncthreads();

    // ======== Pass 2: h2 = tanh(h1 @ W2 + b2) -> B2 ========
    gemm(B1, WB, 32, arow0, c0, acc);
    __syncthreads();
    {
        float4 bb = __ldg(reinterpret_cast<const float4*>(b2e + c0));
#pragma unroll
        for (int ai = 0; ai < 8; ai++) {
            float4 h;
            h.x = fast_tanh(acc[ai][0] + bb.x);
            h.y = fast_tanh(acc[ai][1] + bb.y);
            h.z = fast_tanh(acc[ai][2] + bb.z);
            h.w = fast_tanh(acc[ai][3] + bb.w);
            *reinterpret_cast<float4*>(B2 + (arow0 + ai) * LW + c0) = h;
        }
    }
    stage_fwd(WB, W3e, HID, tid);
    __syncthreads();

    // ======== Pass 3: h3; energy; dp3 = W4*(1-h3^2) -> B0 ========
    gemm(B2, WB, 32, arow0, c0, acc);
    __syncthreads();
    {
        float4 bb = __ldg(reinterpret_cast<const float4*>(b3e + c0));
        float4 w4 = __ldg(reinterpret_cast<const float4*>(W4e + c0));
        float ea[8];
#pragma unroll
        for (int ai = 0; ai < 8; ai++) {
            float4 d;
            float h;
            h = fast_tanh(acc[ai][0] + bb.x); d.x = w4.x * (1.f - h * h);
            float p = h * w4.x;
            h = fast_tanh(acc[ai][1] + bb.y); d.y = w4.y * (1.f - h * h);
            p = fmaf(h, w4.y, p);
            h = fast_tanh(acc[ai][2] + bb.z); d.z = w4.z * (1.f - h * h);
            p = fmaf(h, w4.z, p);
            h = fast_tanh(acc[ai][3] + bb.w); d.w = w4.w * (1.f - h * h);
            p = fmaf(h, w4.w, p);
            ea[ai] = p;
            *reinterpret_cast<float4*>(B0 + (arow0 + ai) * LW + c0) = d;
        }
#pragma unroll
        for (int ai = 0; ai < 8; ai++) {
            float v = ea[ai];
#pragma unroll
            for (int o = 1; o < 32; o <<= 1)
                v += __shfl_xor_sync(0xffffffffu, v, o);
            if (lane == 0) {
                int aid = s_aid[arow0 + ai];
                if (aid >= 0)
                    atomicAdd(&energy[__ldg(img + aid)], v + b4e);
            }
        }
    }
    stage_bwd(WB, W3e, HID, tid);
    __syncthreads();

    // ======== Pass 4: dp2 = (dp3 @ W3^T) * (1 - h2^2), in-place B2 ========
    gemm(B0, WB, 32, arow0, c0, acc);
    __syncthreads();
#pragma unroll
    for (int ai = 0; ai < 8; ai++) {
        float4* p = reinterpret_cast<float4*>(B2 + (arow0 + ai) * LW + c0);
        float4 h = *p;
        h.x = acc[ai][0] * (1.f - h.x * h.x);
        h.y = acc[ai][1] * (1.f - h.y * h.y);
        h.z = acc[ai][2] * (1.f - h.z * h.z);
        h.w = acc[ai][3] * (1.f - h.w * h.w);
        *p = h;
    }
    stage_bwd(WB, W2e, HID, tid);
    __syncthreads();

    // ======== Pass 5: dp1 = (dp2 @ W2^T) * (1 - h1^2), in-place B1 ========
    gemm(B2, WB, 32, arow0, c0, acc);
    __syncthreads();
#pragma unroll
    for (int ai = 0; ai < 8; ai++) {
        float4* p = reinterpret_cast<float4*>(B1 + (arow0 + ai) * LW + c0);
        float4 h = *p;
        h.x = acc[ai][0] * (1.f - h.x * h.x);
        h.y = acc[ai][1] * (1.f - h.y * h.y);
        h.z = acc[ai][2] * (1.f - h.z * h.z);
        h.w = acc[ai][3] * (1.f - h.w * h.w);
        *p = h;
    }
    stage_bwd(WB, W1e, DIN, tid);     // cols m >= 120 staged as zero
    __syncthreads();

    // ======== Pass 6: g = dp1 @ W1^T -> global (cols 0..119) ========
    gemm(B1, WB, 32, arow0, c0, acc);
    if (c0 < DIN) {
#pragma unroll
        for (int ai = 0; ai < 8; ai++) {
            int aid = s_aid[arow0 + ai];
            if (aid >= 0)
                *reinterpret_cast<float4*>(g_flat_d + aid * DIN + c0) =
                    make_float4(acc[ai][0], acc[ai][1], acc[ai][2], acc[ai][3]);
        }
    }
}

// ---------------- sparse force scatter (4-wide) ----------------
__global__ void k_scatter(const int4* __restrict__ rows4,
                          const int4* __restrict__ cols4,
                          const float4* __restrict__ vals4,
                          const int* __restrict__ rows,
                          const int* __restrict__ cols,
                          const float* __restrict__ vals,
                          float* __restrict__ forces, int nnz)
{
    int n4 = nnz >> 2;
    int t = blockIdx.x * blockDim.x + threadIdx.x;
    if (t < n4) {
        int4   r = __ldg(rows4 + t);
        int4   c = __ldg(cols4 + t);
        float4 v = __ldg(vals4 + t);
        atomicAdd(forces + c.x, -v.x * g_flat_d[r.x]);
        atomicAdd(forces + c.y, -v.y * g_flat_d[r.y]);
        atomicAdd(forces + c.z, -v.z * g_flat_d[r.z]);
        atomicAdd(forces + c.w, -v.w * g_flat_d[r.w]);
    }
    if (t == 0) {
        for (int i = n4 << 2; i < nnz; i++)
            atomicAdd(forces + __ldg(cols + i),
                      -__ldg(vals + i) * g_flat_d[__ldg(rows + i)]);
    }
}

// ---------------- launch ----------------
extern "C" void kernel_launch(void* const* d_in, const int* in_sizes, int n_in,
                              void* d_out, int out_size)
{
    const int*   z    = (const int*)  d_in[0];
    const float* fp   = (const float*)d_in[1];
    const int*   img  = (const int*)  d_in[2];
    const int*   rows = (const int*)  d_in[3];
    const int*   cols = (const int*)  d_in[4];
    const float* vals = (const float*)d_in[5];
    int base = (in_sizes[6] == 3 * DIN * HID) ? 6 : 7;
    const float* W1 = (const float*)d_in[base + 0];
    const float* b1 = (const float*)d_in[base + 1];
    const float* W2 = (const float*)d_in[base + 2];
    const float* b2 = (const float*)d_in[base + 3];
    const float* W3 = (const float*)d_in[base + 4];
    const float* b3 = (const float*)d_in[base + 5];
    const float* W4 = (const float*)d_in[base + 6];
    const float* b4 = (const float*)d_in[base + 7];

    float* out    = (float*)d_out;
    float* energy = out;
    float* forces = out + NMOL;
    int nnz = in_sizes[3];

    cudaFuncSetAttribute(k_mlp, cudaFuncAttributeMaxDynamicSharedMemorySize, SMEM_DYN);

    int tot = NMOL + 3 * N_ATOMS;
    k_init   <<<(tot + 255) / 256, 256>>>(out);
    k_count  <<<(N_ATOMS + 255) / 256, 256>>>(z);
    k_build  <<<(N_ATOMS + 255) / 256, 256>>>(z);
    k_mlp    <<<NBLK, NTHR, SMEM_DYN>>>(z, fp, img, W1, b1, W2, b2, W3, b3, W4, b4, energy);
    k_scatter<<<((nnz >> 2) + 255) / 256, 256>>>(
        (const int4*)rows, (const int4*)cols, (const float4*)vals,
        rows, cols, vals, forces, nnz);
}